// round 8
// baseline (speedup 1.0000x reference)
#include <cuda_runtime.h>
#include <cstdint>

#define BB 512
#define NN 90
#define DD 1024
#define KK 45
#define THREADS 1024
#define WARPS 32
#define CLUSTER 4
#define ROWS_PER_CTA 45                      // one (tensor, half) tile
#define BUF_BYTES (ROWS_PER_CTA * DD * 4)    // 184320 B dynamic smem

__device__ unsigned g_task_counter;
__device__ unsigned g_done;

__device__ __forceinline__ uint32_t smem_u32(const void* p) {
    uint32_t a;
    asm("{ .reg .u64 t; cvta.to.shared.u64 t, %1; cvt.u32.u64 %0, t; }"
        : "=r"(a) : "l"(p));
    return a;
}
__device__ __forceinline__ void dsmem_st_u32(uint32_t local_addr, uint32_t peer, unsigned v) {
    uint32_t r;
    asm volatile("mapa.shared::cluster.u32 %0, %1, %2;" : "=r"(r) : "r"(local_addr), "r"(peer));
    asm volatile("st.shared::cluster.u32 [%0], %1;" :: "r"(r), "r"(v) : "memory");
}
__device__ __forceinline__ void dsmem_st_f32(uint32_t local_addr, uint32_t peer, float v) {
    uint32_t r;
    asm volatile("mapa.shared::cluster.u32 %0, %1, %2;" : "=r"(r) : "r"(local_addr), "r"(peer));
    asm volatile("st.shared::cluster.f32 [%0], %1;" :: "r"(r), "f"(v) : "memory");
}
__device__ __forceinline__ void cluster_sync() {
    asm volatile("barrier.cluster.arrive.aligned;" ::: "memory");
    asm volatile("barrier.cluster.wait.aligned;" ::: "memory");
}

__global__ __launch_bounds__(THREADS, 1) __cluster_dims__(CLUSTER, 1, 1)
void multig_pool_kernel(const float* __restrict__ x_sc,
                        const float* __restrict__ x_fc,
                        const float* __restrict__ pool_w,
                        const float* __restrict__ multi_w,
                        const float* __restrict__ multi_b,
                        float* __restrict__ out)
{
    extern __shared__ __align__(16) float4 buf4[];   // 45 rows x 1024 f32
    __shared__ __align__(16) float spw[DD];
    __shared__ float s_alltanh[2 * NN];   // [tensor][node]
    __shared__ float s_part[NN * 2];      // per-(row,half) dot partials -> reused
    __shared__ float s_scores[NN];
    __shared__ int   sel_idx[KK];
    __shared__ float sel_w[KK];
    __shared__ float red[WARPS];
    __shared__ float s_invnorm;
    __shared__ unsigned s_task;

    const int tid  = threadIdx.x;
    const int wid  = tid >> 5;
    const int lane = tid & 31;

    uint32_t rank;
    asm("mov.u32 %0, %%cluster_ctarank;" : "=r"(rank));
    const int tensor = (int)(rank >> 1);     // 0 = sc, 1 = fc
    const int half   = (int)(rank & 1);      // rows [half*45, half*45+45)

    // ---- Once: stage pool_w, 1/||pool_w|| ----
    {
        float v = pool_w[tid];
        spw[tid] = v;
        float pw2 = v * v;
        #pragma unroll
        for (int off = 16; off; off >>= 1) pw2 += __shfl_xor_sync(0xffffffffu, pw2, off);
        if (lane == 0) red[wid] = pw2;
    }
    __syncthreads();
    if (tid == 0) {
        float s = 0.f;
        #pragma unroll
        for (int i = 0; i < WARPS; i++) s += red[i];
        s_invnorm = rsqrtf(s);
    }
    __syncthreads();

    const float inv_norm = s_invnorm;
    const float mw0 = multi_w[0];
    const float mw1 = multi_w[1];
    const float4* __restrict__ pw4 = (const float4*)spw;
    const uint32_t task_addr = smem_u32(&s_task);
    const uint32_t tanh_addr = smem_u32(&s_alltanh[0]);

    const float* __restrict__ X = (tensor == 0) ? x_sc : x_fc;
    float* __restrict__ OUT_T   = out + (size_t)tensor * BB * KK * DD;

    // ---- Persistent loop: one 4-CTA cluster = one batch ----
    for (;;) {
        if (rank == 0 && tid == 0) {
            unsigned t = atomicAdd(&g_task_counter, 1u);
            s_task = t;
            dsmem_st_u32(task_addr, 1u, t);
            dsmem_st_u32(task_addr, 2u, t);
            dsmem_st_u32(task_addr, 3u, t);
        }
        // SYNC A: publishes s_task; also protects buf4/s_* reuse across iters
        // (cluster barrier subsumes __syncthreads).
        cluster_sync();
        const unsigned b = s_task;   // local smem read only (exit-safe)
        if (b >= BB) break;

        // My 45-row tile: rows [half*45, half*45+45) of tensor X, batch b.
        const float4* __restrict__ src4 =
            (const float4*)(X + (size_t)b * NN * DD + (size_t)half * ROWS_PER_CTA * DD);

        // ===== Stream tile: LDG -> dot partial + STS to smem buffer =====
        // 90 half-row tasks (45 rows x 2 halves of 512 floats), warp each.
        for (int t = wid; t < 2 * ROWS_PER_CTA; t += WARPS) {
            const int r = t >> 1;
            const int h = t & 1;
            const int base = r * 256 + h * 128;   // float4 index of half-row
            float d = 0.f;
            #pragma unroll
            for (int m = 0; m < 4; m++) {
                const int j = lane + m * 32;      // 0..127
                float4 a = src4[base + j];
                float4 p = pw4[h * 128 + j];
                buf4[base + j] = a;
                d += a.x * p.x + a.y * p.y + a.z * p.z + a.w * p.w;
            }
            #pragma unroll
            for (int off = 16; off; off >>= 1) d += __shfl_xor_sync(0xffffffffu, d, off);
            if (lane == 0) s_part[t] = d;
        }
        __syncthreads();

        // ===== tanh for my 45 rows; publish to own + 3 peers =====
        if (tid < ROWS_PER_CTA) {
            float t0 = tanhf((s_part[2 * tid] + s_part[2 * tid + 1]) * inv_norm);
            const int node = half * ROWS_PER_CTA + tid;
            const uint32_t off = (uint32_t)(tensor * NN + node) * 4u;
            s_alltanh[tensor * NN + node] = t0;
            #pragma unroll
            for (uint32_t p = 0; p < CLUSTER; p++)
                if (p != rank) dsmem_st_f32(tanh_addr + off, p, t0);
        }
        // SYNC B: all 180 tanh values visible everywhere.
        cluster_sync();

        // ===== Scores + top-45 selection (redundant per CTA, cheap) =====
        if (tid < NN) {
            float z = s_alltanh[tid] * mw0 + s_alltanh[NN + tid] * mw1 + multi_b[tid];
            s_scores[tid] = 1.f / (1.f + expf(-z));
        }
        __syncthreads();
        if (tid < NN) {
            float my = s_scores[tid];
            int r = 0;
            #pragma unroll 10
            for (int j = 0; j < NN; j++) {
                float sj = s_scores[j];
                r += (sj > my) || (sj == my && j < tid);
            }
            if (r < KK) { sel_idx[r] = tid; sel_w[r] = my; }
        }
        __syncthreads();

        // ===== Write selected rows I own, straight from smem =====
        float* __restrict__ ob = OUT_T + (size_t)b * KK * DD;
        for (int k = wid; k < KK; k += WARPS) {
            const int n = sel_idx[k];
            const int local = n - half * ROWS_PER_CTA;
            if ((unsigned)local < (unsigned)ROWS_PER_CTA) {
                const float w = sel_w[k];
                const float4* srow = buf4 + (size_t)local * 256;
                float4* dst = (float4*)(ob + (size_t)k * DD);
                #pragma unroll
                for (int m = 0; m < 8; m++) {
                    const int j = lane + m * 32;
                    float4 v = srow[j];
                    v.x *= w; v.y *= w; v.z *= w; v.w *= w;
                    dst[j] = v;
                }
            }
        }
        // loop back: SYNC A protects buf4 before next iteration's STS
    }

    // Exit barrier: no CTA leaves while a peer might still push to its smem.
    cluster_sync();

    // ---- Last CTA resets device state for the next graph replay ----
    if (tid == 0) {
        unsigned d = atomicAdd(&g_done, 1u) + 1u;
        if (d == gridDim.x) {
            g_task_counter = 0;
            g_done = 0;
        }
    }
}

extern "C" void kernel_launch(void* const* d_in, const int* in_sizes, int n_in,
                              void* d_out, int out_size)
{
    const float* x_sc    = (const float*)d_in[0];
    const float* x_fc    = (const float*)d_in[1];
    const float* pool_w  = (const float*)d_in[2];
    const float* multi_w = (const float*)d_in[3];
    const float* multi_b = (const float*)d_in[4];
    float* out = (float*)d_out;

    static int inited = 0;
    if (!inited) {
        cudaFuncSetAttribute(multig_pool_kernel,
                             cudaFuncAttributeMaxDynamicSharedMemorySize, BUF_BYTES);
        inited = 1;
    }

    // 33 clusters x 4 CTAs = 132 CTAs (cluster-4 residency cap per B300 docs).
    multig_pool_kernel<<<132, THREADS, BUF_BYTES>>>(x_sc, x_fc, pool_w, multi_w, multi_b, out);
}